// round 2
// baseline (speedup 1.0000x reference)
#include <cuda_runtime.h>
#include <math.h>

// Problem dims (fixed by the dataset)
#define SEQ   1024
#define BATCH 16
#define DIM   1024
#define HDIM  1024
#define MDIM  (SEQ * BATCH)     // 16384 rows of the GEMM
#define NDIM  (3 * HDIM)        // 3072 cols of the GEMM
#define KDIM  DIM               // 1024

// Scratch: activated gate planes, each [M, H] fp32 (64 MB apiece).
__device__ float g_Z[MDIM * HDIM];   // tanh(z)
__device__ float g_F[MDIM * HDIM];   // sigmoid(f)
__device__ float g_O[MDIM * HDIM];   // sigmoid(o)

// ---------------------------------------------------------------------------
// GEMM: Y[m,n] = sum_k X[m,k] * W[n,k] + b[n], fused activation epilogue.
// Both operands are K-major (row-major [M,K] and [N,K]) -> coalesced loads.
// Tile: 128x128x16, 256 threads, 8x8 accumulators per thread.
// ---------------------------------------------------------------------------
#define BM 128
#define BN 128
#define BK 16

__global__ __launch_bounds__(256, 2) void gemm_act_kernel(
    const float* __restrict__ X,
    const float* __restrict__ W,
    const float* __restrict__ bias)
{
    __shared__ float As[BK][BM];
    __shared__ float Bs[BK][BN];

    const int tid = threadIdx.x;
    const int bm  = blockIdx.y * BM;
    const int bn  = blockIdx.x * BN;

    const int tx = tid & 15;   // N direction, 0..15
    const int ty = tid >> 4;   // M direction, 0..15

    float acc[8][8];
    #pragma unroll
    for (int i = 0; i < 8; i++)
        #pragma unroll
        for (int j = 0; j < 8; j++)
            acc[i][j] = 0.0f;

    // Each thread loads 2 float4 of A and 2 float4 of B per K-step.
    // Tile has 128 rows x 4 float4 per row = 512 float4; 256 threads -> 2 each.
    const int ldrow0 = tid >> 2;          // 0..63
    const int ldcol4 = tid & 3;           // 0..3 (which float4 in the row)

    for (int k0 = 0; k0 < KDIM; k0 += BK) {
        #pragma unroll
        for (int r = 0; r < 2; r++) {
            int row = ldrow0 + r * 64;
            float4 a = *reinterpret_cast<const float4*>(
                &X[(size_t)(bm + row) * KDIM + k0 + ldcol4 * 4]);
            As[ldcol4 * 4 + 0][row] = a.x;
            As[ldcol4 * 4 + 1][row] = a.y;
            As[ldcol4 * 4 + 2][row] = a.z;
            As[ldcol4 * 4 + 3][row] = a.w;

            float4 bq = *reinterpret_cast<const float4*>(
                &W[(size_t)(bn + row) * KDIM + k0 + ldcol4 * 4]);
            Bs[ldcol4 * 4 + 0][row] = bq.x;
            Bs[ldcol4 * 4 + 1][row] = bq.y;
            Bs[ldcol4 * 4 + 2][row] = bq.z;
            Bs[ldcol4 * 4 + 3][row] = bq.w;
        }
        __syncthreads();

        #pragma unroll
        for (int k = 0; k < BK; k++) {
            float areg[8], breg[8];
            float4 a0 = *reinterpret_cast<const float4*>(&As[k][ty * 8]);
            float4 a1 = *reinterpret_cast<const float4*>(&As[k][ty * 8 + 4]);
            float4 b0 = *reinterpret_cast<const float4*>(&Bs[k][tx * 8]);
            float4 b1 = *reinterpret_cast<const float4*>(&Bs[k][tx * 8 + 4]);
            areg[0]=a0.x; areg[1]=a0.y; areg[2]=a0.z; areg[3]=a0.w;
            areg[4]=a1.x; areg[5]=a1.y; areg[6]=a1.z; areg[7]=a1.w;
            breg[0]=b0.x; breg[1]=b0.y; breg[2]=b0.z; breg[3]=b0.w;
            breg[4]=b1.x; breg[5]=b1.y; breg[6]=b1.z; breg[7]=b1.w;
            #pragma unroll
            for (int i = 0; i < 8; i++)
                #pragma unroll
                for (int j = 0; j < 8; j++)
                    acc[i][j] = fmaf(areg[i], breg[j], acc[i][j]);
        }
        __syncthreads();
    }

    // Epilogue: bias + activation, scatter to the right gate plane.
    // BN=128 divides HDIM=1024, so an output tile lives in exactly one channel.
    const int nch  = bn / HDIM;          // 0 = Z(tanh), 1 = F(sigmoid), 2 = O(sigmoid)
    const int hoff = bn - nch * HDIM;
    float* dst = (nch == 0) ? g_Z : (nch == 1) ? g_F : g_O;

    #pragma unroll
    for (int i = 0; i < 8; i++) {
        const int r = bm + ty * 8 + i;
        #pragma unroll
        for (int j = 0; j < 8; j++) {
            const int cc = tx * 8 + j;            // column within tile
            const float y = acc[i][j] + bias[bn + cc];
            float v;
            if (nch == 0) v = tanhf(y);
            else          v = 1.0f / (1.0f + expf(-y));
            dst[(size_t)r * HDIM + hoff + cc] = v;
        }
    }
}

// ---------------------------------------------------------------------------
// Scan: h_t = f_t*z_t + (1-f_t)*h_{t-1}, Hout_t = o_t * h_t.
// One thread per (b,h) chain; 16384 chains, stride BATCH*HDIM per step
// -> fully coalesced across threads at every timestep.
// ---------------------------------------------------------------------------
__global__ __launch_bounds__(256) void scan_kernel(float* __restrict__ out)
{
    const int chain = blockIdx.x * blockDim.x + threadIdx.x;  // 0..16383 == b*HDIM + h
    float h = 0.0f;
    size_t idx = chain;
    for (int s = 0; s < SEQ; s++, idx += (size_t)BATCH * HDIM) {
        const float f = g_F[idx];
        const float z = g_Z[idx];
        const float o = g_O[idx];
        h = fmaf(f, z - h, h);     // f*z + (1-f)*h
        out[idx] = o * h;
    }
    // C[-1] appended after Hout: offset S*B*H
    out[(size_t)MDIM * HDIM + chain] = h;
}

extern "C" void kernel_launch(void* const* d_in, const int* in_sizes, int n_in,
                              void* d_out, int out_size)
{
    const float* X    = (const float*)d_in[0];
    const float* W    = (const float*)d_in[1];
    const float* bias = (const float*)d_in[2];
    float* out = (float*)d_out;

    dim3 grid(NDIM / BN, MDIM / BM);   // (24, 128) = 3072 blocks
    gemm_act_kernel<<<grid, 256>>>(X, W, bias);
    scan_kernel<<<(BATCH * HDIM) / 256, 256>>>(out);
}

// round 4
// speedup vs baseline: 4.5174x; 4.5174x over previous
#include <cuda_runtime.h>
#include <cuda_bf16.h>
#include <cstdint>
#include <math.h>

// ---------------------------------------------------------------------------
// Problem dims (fixed)
// ---------------------------------------------------------------------------
#define SEQ   1024
#define BATCH 16
#define HDIM  1024
#define KDIM  1024
#define MDIM  (SEQ * BATCH)     // 16384
#define NDIM  (3 * HDIM)        // 3072

// ---------------------------------------------------------------------------
// Device scratch (static only)
// ---------------------------------------------------------------------------
__device__ float g_Z[(size_t)MDIM * HDIM];
__device__ float g_F[(size_t)MDIM * HDIM];
__device__ float g_O[(size_t)MDIM * HDIM];

__device__ __nv_bfloat16 g_Xhi[(size_t)MDIM * KDIM];
__device__ __nv_bfloat16 g_Xlo[(size_t)MDIM * KDIM];
__device__ __nv_bfloat16 g_Whi[(size_t)NDIM * KDIM];
__device__ __nv_bfloat16 g_Wlo[(size_t)NDIM * KDIM];

#define NCHUNK 16
#define CLEN   64               // SEQ / NCHUNK
#define NCHAIN (BATCH * HDIM)   // 16384
__device__ float g_cA[NCHUNK * NCHAIN];
__device__ float g_cB[NCHUNK * NCHAIN];
__device__ float g_cH[NCHUNK * NCHAIN];

// ---------------------------------------------------------------------------
// Helpers
// ---------------------------------------------------------------------------
static __device__ __forceinline__ uint32_t smem_u32(const void* p) {
    uint32_t a;
    asm("{ .reg .u64 t; cvta.to.shared.u64 t, %1; cvt.u32.u64 %0, t; }"
        : "=r"(a) : "l"(p));
    return a;
}

static __device__ __forceinline__ void cp16(uint32_t saddr, const void* gaddr) {
    asm volatile("cp.async.cg.shared.global [%0], [%1], 16;"
                 :: "r"(saddr), "l"(gaddr) : "memory");
}
#define CP_COMMIT() asm volatile("cp.async.commit_group;" ::: "memory")
#define CP_WAIT1()  asm volatile("cp.async.wait_group 1;" ::: "memory")

static __device__ __forceinline__ void ldsm4(uint32_t* r, uint32_t addr) {
    asm volatile("ldmatrix.sync.aligned.m8n8.x4.shared.b16 {%0,%1,%2,%3}, [%4];"
                 : "=r"(r[0]), "=r"(r[1]), "=r"(r[2]), "=r"(r[3]) : "r"(addr));
}

static __device__ __forceinline__ void mma16816(float* d, const uint32_t* a,
                                                const uint32_t* b) {
    asm volatile(
        "mma.sync.aligned.m16n8k16.row.col.f32.bf16.bf16.f32 "
        "{%0,%1,%2,%3}, {%4,%5,%6,%7}, {%8,%9}, {%0,%1,%2,%3};"
        : "+f"(d[0]), "+f"(d[1]), "+f"(d[2]), "+f"(d[3])
        : "r"(a[0]), "r"(a[1]), "r"(a[2]), "r"(a[3]), "r"(b[0]), "r"(b[1]));
}

// ---------------------------------------------------------------------------
// fp32 -> bf16 hi/lo split
// ---------------------------------------------------------------------------
template <bool ISX>
__global__ __launch_bounds__(256) void split_kernel(const float4* __restrict__ src) {
    int i = blockIdx.x * 256 + threadIdx.x;
    float4 v = src[i];
    __nv_bfloat16 hx = __float2bfloat16(v.x);
    __nv_bfloat16 hy = __float2bfloat16(v.y);
    __nv_bfloat16 hz = __float2bfloat16(v.z);
    __nv_bfloat16 hw = __float2bfloat16(v.w);
    __nv_bfloat162* hi = (__nv_bfloat162*)(ISX ? g_Xhi : g_Whi);
    __nv_bfloat162* lo = (__nv_bfloat162*)(ISX ? g_Xlo : g_Wlo);
    hi[2 * i + 0] = __halves2bfloat162(hx, hy);
    hi[2 * i + 1] = __halves2bfloat162(hz, hw);
    lo[2 * i + 0] = __halves2bfloat162(
        __float2bfloat16(v.x - __bfloat162float(hx)),
        __float2bfloat16(v.y - __bfloat162float(hy)));
    lo[2 * i + 1] = __halves2bfloat162(
        __float2bfloat16(v.z - __bfloat162float(hz)),
        __float2bfloat16(v.w - __bfloat162float(hw)));
}

// ---------------------------------------------------------------------------
// HMMA GEMM: 128x128 tile, BK=64, 3-stage cp.async pipeline.
// Y[m,n] = sum_k X[m,k]*W[n,k] + b[n]; 3-term bf16 split; fused activation.
// smem rows are 64 bf16 = 128B; swizzle: 16B group g at row r -> g ^ (r&7).
// ---------------------------------------------------------------------------
#define BM 128
#define BN 128
#define BK 64
#define PLANE_BYTES (128 * 128)          // 128 rows x 128B
#define STAGE_BYTES (4 * PLANE_BYTES)    // Ahi, Alo, Bhi, Blo
#define NSTAGE 3
#define GEMM_SMEM (NSTAGE * STAGE_BYTES)
#define NCHK (KDIM / BK)                 // 16

#define OFF_AHI 0
#define OFF_ALO PLANE_BYTES
#define OFF_BHI (2 * PLANE_BYTES)
#define OFF_BLO (3 * PLANE_BYTES)

__global__ __launch_bounds__(256, 1) void gemm_hmma_kernel(
    const float* __restrict__ bias)
{
    extern __shared__ char sm[];
    const uint32_t sbase = smem_u32(sm);

    const int tid = threadIdx.x;
    const int wid = tid >> 5;
    const int lid = tid & 31;
    const int bm = blockIdx.y * BM;
    const int bn = blockIdx.x * BN;

    // warp tiling: 4 (m) x 2 (n); warp tile 32m x 64n
    const int wm = wid >> 1;
    const int wn = wid & 1;

    float acc[2][8][4];
    #pragma unroll
    for (int i = 0; i < 2; i++)
        #pragma unroll
        for (int j = 0; j < 8; j++)
            #pragma unroll
            for (int q = 0; q < 4; q++)
                acc[i][j][q] = 0.0f;

    // ---- cp.async loader: each thread does 4 chunks per plane per stage ----
    const int lrow = tid >> 1;            // base pattern: 1024 chunks/plane
    auto load_stage = [&](int c, int s) {
        const uint32_t sb = sbase + s * STAGE_BYTES;
        const int k0 = c * BK;
        #pragma unroll
        for (int i = 0; i < 4; i++) {
            const int u = tid + i * 256;          // 0..1023
            const int row = u >> 3;
            const int kg = u & 7;
            const uint32_t so = row * 128 + 16 * (kg ^ (row & 7));
            const size_t gx = ((size_t)(bm + row) * KDIM + k0 + kg * 8) * 2;
            const size_t gw = ((size_t)(bn + row) * KDIM + k0 + kg * 8) * 2;
            cp16(sb + OFF_AHI + so, (const char*)g_Xhi + gx);
            cp16(sb + OFF_ALO + so, (const char*)g_Xlo + gx);
            cp16(sb + OFF_BHI + so, (const char*)g_Whi + gw);
            cp16(sb + OFF_BLO + so, (const char*)g_Wlo + gw);
        }
    };

    // ldmatrix per-lane address pieces
    // A x4 at (m0, kf): lanes 0-15 -> row m0+(l&15), kgrp 2kf; lanes16-31 -> row m0+(l&15), kgrp 2kf+1
    const int a_rl = lid & 15;
    const int a_kh = lid >> 4;            // 0 or 1
    // B x4 at (n0, kf): row n0 + (l&7) + ((l&16)>>1), kgrp 2kf + ((l>>3)&1)
    const int b_rl = (lid & 7) + ((lid & 16) >> 1);
    const int b_kh = (lid >> 3) & 1;

    // prologue
    load_stage(0, 0); CP_COMMIT();
    load_stage(1, 1); CP_COMMIT();

    for (int c = 0; c < NCHK; c++) {
        CP_WAIT1();
        __syncthreads();
        if (c + 2 < NCHK) load_stage(c + 2, (c + 2) % NSTAGE);
        CP_COMMIT();

        const uint32_t sb = sbase + (c % NSTAGE) * STAGE_BYTES;

        #pragma unroll
        for (int kf = 0; kf < 4; kf++) {
            uint32_t ahi[2][4], alo[2][4], bhi[8][2], blo[8][2];

            #pragma unroll
            for (int mf = 0; mf < 2; mf++) {
                const int row = wm * 32 + mf * 16 + a_rl;
                const int kg = 2 * kf + a_kh;
                const uint32_t so = row * 128 + 16 * (kg ^ (row & 7));
                ldsm4(ahi[mf], sb + OFF_AHI + so);
                ldsm4(alo[mf], sb + OFF_ALO + so);
            }
            #pragma unroll
            for (int nq = 0; nq < 4; nq++) {
                const int row = wn * 64 + nq * 16 + b_rl;
                const int kg = 2 * kf + b_kh;
                const uint32_t so = row * 128 + 16 * (kg ^ (row & 7));
                uint32_t t[4];
                ldsm4(t, sb + OFF_BHI + so);
                bhi[nq * 2][0] = t[0]; bhi[nq * 2][1] = t[1];
                bhi[nq * 2 + 1][0] = t[2]; bhi[nq * 2 + 1][1] = t[3];
                ldsm4(t, sb + OFF_BLO + so);
                blo[nq * 2][0] = t[0]; blo[nq * 2][1] = t[1];
                blo[nq * 2 + 1][0] = t[2]; blo[nq * 2 + 1][1] = t[3];
            }

            #pragma unroll
            for (int mf = 0; mf < 2; mf++)
                #pragma unroll
                for (int nf = 0; nf < 8; nf++)
                    mma16816(acc[mf][nf], ahi[mf], bhi[nf]);
            #pragma unroll
            for (int mf = 0; mf < 2; mf++)
                #pragma unroll
                for (int nf = 0; nf < 8; nf++)
                    mma16816(acc[mf][nf], ahi[mf], blo[nf]);
            #pragma unroll
            for (int mf = 0; mf < 2; mf++)
                #pragma unroll
                for (int nf = 0; nf < 8; nf++)
                    mma16816(acc[mf][nf], alo[mf], bhi[nf]);
        }
        __syncthreads();
    }

    // ---- epilogue: bias + activation, direct store to gate plane ----
    const int nch  = bn >> 10;                 // 0=Z(tanh), 1=F, 2=O (sigmoid)
    const int hoff = bn & 1023;
    float* dst = (nch == 0) ? g_Z : (nch == 1) ? g_F : g_O;
    const float* bp = bias + bn + wn * 64;

    #pragma unroll
    for (int mf = 0; mf < 2; mf++) {
        const int r0 = bm + wm * 32 + mf * 16 + (lid >> 2);
        #pragma unroll
        for (int nf = 0; nf < 8; nf++) {
            const int col = nf * 8 + (lid & 3) * 2;
            const float b0 = __ldg(bp + col);
            const float b1 = __ldg(bp + col + 1);
            #pragma unroll
            for (int half = 0; half < 2; half++) {
                const int r = r0 + half * 8;
                float y0 = acc[mf][nf][2 * half + 0] + b0;
                float y1 = acc[mf][nf][2 * half + 1] + b1;
                float v0, v1;
                if (nch == 0) { v0 = tanhf(y0); v1 = tanhf(y1); }
                else {
                    v0 = 1.0f / (1.0f + __expf(-y0));
                    v1 = 1.0f / (1.0f + __expf(-y1));
                }
                *(float2*)&dst[(size_t)r * HDIM + hoff + wn * 64 + col] =
                    make_float2(v0, v1);
            }
        }
    }
}

// ---------------------------------------------------------------------------
// Chunked scan: h_t = f_t*z_t + (1-f_t)*h_{t-1}
// ---------------------------------------------------------------------------
__global__ __launch_bounds__(256) void scan_chunks_kernel() {
    const int chain = blockIdx.x * 256 + threadIdx.x;
    const int ck = blockIdx.y;
    size_t idx = (size_t)ck * CLEN * NCHAIN + chain;
    float A = 1.0f, Bv = 0.0f;
    #pragma unroll 4
    for (int s = 0; s < CLEN; s++, idx += NCHAIN) {
        const float f = g_F[idx];
        const float z = g_Z[idx];
        Bv = fmaf(f, z - Bv, Bv);
        A *= (1.0f - f);
    }
    g_cA[ck * NCHAIN + chain] = A;
    g_cB[ck * NCHAIN + chain] = Bv;
}

__global__ __launch_bounds__(256) void scan_combine_kernel() {
    const int chain = blockIdx.x * 256 + threadIdx.x;
    float h = 0.0f;
    #pragma unroll
    for (int c = 0; c < NCHUNK; c++) {
        g_cH[c * NCHAIN + chain] = h;
        h = fmaf(g_cA[c * NCHAIN + chain], h, g_cB[c * NCHAIN + chain]);
    }
}

__global__ __launch_bounds__(256) void scan_final_kernel(float* __restrict__ out) {
    const int chain = blockIdx.x * 256 + threadIdx.x;
    const int ck = blockIdx.y;
    size_t idx = (size_t)ck * CLEN * NCHAIN + chain;
    float h = g_cH[ck * NCHAIN + chain];
    #pragma unroll 4
    for (int s = 0; s < CLEN; s++, idx += NCHAIN) {
        const float f = g_F[idx];
        const float z = g_Z[idx];
        const float o = g_O[idx];
        h = fmaf(f, z - h, h);
        out[idx] = o * h;
    }
    if (ck == NCHUNK - 1)
        out[(size_t)MDIM * HDIM + chain] = h;   // C[-1]
}

// ---------------------------------------------------------------------------
extern "C" void kernel_launch(void* const* d_in, const int* in_sizes, int n_in,
                              void* d_out, int out_size) {
    const float* X    = (const float*)d_in[0];
    const float* W    = (const float*)d_in[1];
    const float* bias = (const float*)d_in[2];
    float* out = (float*)d_out;

    cudaFuncSetAttribute(gemm_hmma_kernel,
                         cudaFuncAttributeMaxDynamicSharedMemorySize, GEMM_SMEM);

    split_kernel<true><<<(MDIM * KDIM / 4) / 256, 256>>>((const float4*)X);
    split_kernel<false><<<(NDIM * KDIM / 4) / 256, 256>>>((const float4*)W);

    dim3 ggrid(NDIM / BN, MDIM / BM);   // (24, 128)
    gemm_hmma_kernel<<<ggrid, 256, GEMM_SMEM>>>(bias);

    dim3 sgrid(NCHAIN / 256, NCHUNK);   // (64, 16)
    scan_chunks_kernel<<<sgrid, 256>>>();
    scan_combine_kernel<<<NCHAIN / 256, 256>>>();
    scan_final_kernel<<<sgrid, 256>>>(out);
}

// round 5
// speedup vs baseline: 10.4676x; 2.3172x over previous
#include <cuda_runtime.h>
#include <cuda_fp16.h>
#include <cstdint>
#include <math.h>

// ---------------------------------------------------------------------------
// Problem dims (fixed)
// ---------------------------------------------------------------------------
#define SEQ   1024
#define BATCH 16
#define HDIM  1024
#define KDIM  1024
#define MDIM  (SEQ * BATCH)     // 16384
#define NDIM  (3 * HDIM)        // 3072

// ---------------------------------------------------------------------------
// Device scratch (static only)
// ---------------------------------------------------------------------------
__device__ float g_Z[(size_t)MDIM * HDIM];
__device__ float g_F[(size_t)MDIM * HDIM];
__device__ float g_O[(size_t)MDIM * HDIM];

__device__ __half g_Xh[(size_t)MDIM * KDIM];
__device__ __half g_Wh[(size_t)NDIM * KDIM];

#define NCHUNK 16
#define CLEN   64               // SEQ / NCHUNK
#define NCHAIN (BATCH * HDIM)   // 16384
__device__ float g_cA[NCHUNK * NCHAIN];
__device__ float g_cB[NCHUNK * NCHAIN];
__device__ float g_cH[NCHUNK * NCHAIN];

// ---------------------------------------------------------------------------
// Helpers
// ---------------------------------------------------------------------------
static __device__ __forceinline__ uint32_t smem_u32(const void* p) {
    uint32_t a;
    asm("{ .reg .u64 t; cvta.to.shared.u64 t, %1; cvt.u32.u64 %0, t; }"
        : "=r"(a) : "l"(p));
    return a;
}

static __device__ __forceinline__ void cp16(uint32_t saddr, const void* gaddr) {
    asm volatile("cp.async.cg.shared.global [%0], [%1], 16;"
                 :: "r"(saddr), "l"(gaddr) : "memory");
}
#define CP_COMMIT() asm volatile("cp.async.commit_group;" ::: "memory")
#define CP_WAIT1()  asm volatile("cp.async.wait_group 1;" ::: "memory")

static __device__ __forceinline__ void ldsm4(uint32_t* r, uint32_t addr) {
    asm volatile("ldmatrix.sync.aligned.m8n8.x4.shared.b16 {%0,%1,%2,%3}, [%4];"
                 : "=r"(r[0]), "=r"(r[1]), "=r"(r[2]), "=r"(r[3]) : "r"(addr));
}

static __device__ __forceinline__ void mma16816(float* d, const uint32_t* a,
                                                const uint32_t* b) {
    asm volatile(
        "mma.sync.aligned.m16n8k16.row.col.f32.f16.f16.f32 "
        "{%0,%1,%2,%3}, {%4,%5,%6,%7}, {%8,%9}, {%0,%1,%2,%3};"
        : "+f"(d[0]), "+f"(d[1]), "+f"(d[2]), "+f"(d[3])
        : "r"(a[0]), "r"(a[1]), "r"(a[2]), "r"(a[3]), "r"(b[0]), "r"(b[1]));
}

// ---------------------------------------------------------------------------
// fp32 -> fp16 conversion prepass
// ---------------------------------------------------------------------------
template <bool ISX>
__global__ __launch_bounds__(256) void conv_kernel(const float4* __restrict__ src) {
    int i = blockIdx.x * 256 + threadIdx.x;
    float4 v = src[i];
    __half2* dst = (__half2*)(ISX ? g_Xh : g_Wh);
    dst[2 * i + 0] = __floats2half2_rn(v.x, v.y);
    dst[2 * i + 1] = __floats2half2_rn(v.z, v.w);
}

// ---------------------------------------------------------------------------
// HMMA GEMM: 128x128 tile, BK=64, 3-stage cp.async pipeline, single fp16 pass.
// Y[m,n] = sum_k X[m,k]*W[n,k] + b[n]; fused bias + activation epilogue.
// smem rows are 64 fp16 = 128B; swizzle: 16B group g at row r -> g ^ (r&7).
// ---------------------------------------------------------------------------
#define BM 128
#define BN 128
#define BK 64
#define PLANE_BYTES (128 * 128)          // 128 rows x 128B
#define STAGE_BYTES (2 * PLANE_BYTES)    // A, B
#define NSTAGE 3
#define GEMM_SMEM (NSTAGE * STAGE_BYTES) // 96 KB -> 2 CTAs/SM
#define NCHK (KDIM / BK)                 // 16

#define OFF_A 0
#define OFF_B PLANE_BYTES

__global__ __launch_bounds__(256, 2) void gemm_hmma_kernel(
    const float* __restrict__ bias)
{
    extern __shared__ char sm[];
    const uint32_t sbase = smem_u32(sm);

    const int tid = threadIdx.x;
    const int wid = tid >> 5;
    const int lid = tid & 31;
    const int bm = blockIdx.y * BM;
    const int bn = blockIdx.x * BN;

    // warp tiling: 4 (m) x 2 (n); warp tile 32m x 64n
    const int wm = wid >> 1;
    const int wn = wid & 1;

    float acc[2][8][4];
    #pragma unroll
    for (int i = 0; i < 2; i++)
        #pragma unroll
        for (int j = 0; j < 8; j++)
            #pragma unroll
            for (int q = 0; q < 4; q++)
                acc[i][j][q] = 0.0f;

    auto load_stage = [&](int c, int s) {
        const uint32_t sb = sbase + s * STAGE_BYTES;
        const int k0 = c * BK;
        #pragma unroll
        for (int i = 0; i < 4; i++) {
            const int u = tid + i * 256;          // 0..1023
            const int row = u >> 3;
            const int kg = u & 7;
            const uint32_t so = row * 128 + 16 * (kg ^ (row & 7));
            const size_t gx = ((size_t)(bm + row) * KDIM + k0 + kg * 8) * 2;
            const size_t gw = ((size_t)(bn + row) * KDIM + k0 + kg * 8) * 2;
            cp16(sb + OFF_A + so, (const char*)g_Xh + gx);
            cp16(sb + OFF_B + so, (const char*)g_Wh + gw);
        }
    };

    // ldmatrix per-lane address pieces
    const int a_rl = lid & 15;
    const int a_kh = lid >> 4;            // 0 or 1
    const int b_rl = (lid & 7) + ((lid & 16) >> 1);
    const int b_kh = (lid >> 3) & 1;

    // prologue
    load_stage(0, 0); CP_COMMIT();
    load_stage(1, 1); CP_COMMIT();

    for (int c = 0; c < NCHK; c++) {
        CP_WAIT1();
        __syncthreads();    // orders prior compute before buffer reuse below
        if (c + 2 < NCHK) load_stage(c + 2, (c + 2) % NSTAGE);
        CP_COMMIT();

        const uint32_t sb = sbase + (c % NSTAGE) * STAGE_BYTES;

        #pragma unroll
        for (int kf = 0; kf < 4; kf++) {
            uint32_t a[2][4], b[8][2];

            #pragma unroll
            for (int mf = 0; mf < 2; mf++) {
                const int row = wm * 32 + mf * 16 + a_rl;
                const int kg = 2 * kf + a_kh;
                const uint32_t so = row * 128 + 16 * (kg ^ (row & 7));
                ldsm4(a[mf], sb + OFF_A + so);
            }
            #pragma unroll
            for (int nq = 0; nq < 4; nq++) {
                const int row = wn * 64 + nq * 16 + b_rl;
                const int kg = 2 * kf + b_kh;
                const uint32_t so = row * 128 + 16 * (kg ^ (row & 7));
                uint32_t t[4];
                ldsm4(t, sb + OFF_B + so);
                b[nq * 2][0] = t[0]; b[nq * 2][1] = t[1];
                b[nq * 2 + 1][0] = t[2]; b[nq * 2 + 1][1] = t[3];
            }

            #pragma unroll
            for (int mf = 0; mf < 2; mf++)
                #pragma unroll
                for (int nf = 0; nf < 8; nf++)
                    mma16816(acc[mf][nf], a[mf], b[nf]);
        }
    }

    // ---- epilogue: bias + activation, direct store to gate plane ----
    const int nch  = bn >> 10;                 // 0=Z(tanh), 1=F, 2=O (sigmoid)
    const int hoff = bn & 1023;
    float* dst = (nch == 0) ? g_Z : (nch == 1) ? g_F : g_O;
    const float* bp = bias + bn + wn * 64;

    #pragma unroll
    for (int mf = 0; mf < 2; mf++) {
        const int r0 = bm + wm * 32 + mf * 16 + (lid >> 2);
        #pragma unroll
        for (int nf = 0; nf < 8; nf++) {
            const int col = nf * 8 + (lid & 3) * 2;
            const float b0 = __ldg(bp + col);
            const float b1 = __ldg(bp + col + 1);
            #pragma unroll
            for (int half = 0; half < 2; half++) {
                const int r = r0 + half * 8;
                float y0 = acc[mf][nf][2 * half + 0] + b0;
                float y1 = acc[mf][nf][2 * half + 1] + b1;
                float v0, v1;
                if (nch == 0) { v0 = tanhf(y0); v1 = tanhf(y1); }
                else {
                    v0 = 1.0f / (1.0f + __expf(-y0));
                    v1 = 1.0f / (1.0f + __expf(-y1));
                }
                *(float2*)&dst[(size_t)r * HDIM + hoff + wn * 64 + col] =
                    make_float2(v0, v1);
            }
        }
    }
}

// ---------------------------------------------------------------------------
// Chunked scan, float4-vectorized (4 chains per thread).
// h_t = f_t*z_t + (1-f_t)*h_{t-1}
// ---------------------------------------------------------------------------
#define NC4 (NCHAIN / 4)   // 4096 chain-groups

__global__ __launch_bounds__(256) void scan_chunks_kernel() {
    const int c4 = blockIdx.x * 256 + threadIdx.x;   // 0..4095
    const int ck = blockIdx.y;
    const float4* F4 = (const float4*)g_F;
    const float4* Z4 = (const float4*)g_Z;
    size_t idx = (size_t)ck * CLEN * NC4 + c4;
    float4 A = make_float4(1.f, 1.f, 1.f, 1.f);
    float4 Bv = make_float4(0.f, 0.f, 0.f, 0.f);
    #pragma unroll 4
    for (int s = 0; s < CLEN; s++, idx += NC4) {
        const float4 f = F4[idx];
        const float4 z = Z4[idx];
        Bv.x = fmaf(f.x, z.x - Bv.x, Bv.x); A.x *= (1.0f - f.x);
        Bv.y = fmaf(f.y, z.y - Bv.y, Bv.y); A.y *= (1.0f - f.y);
        Bv.z = fmaf(f.z, z.z - Bv.z, Bv.z); A.z *= (1.0f - f.z);
        Bv.w = fmaf(f.w, z.w - Bv.w, Bv.w); A.w *= (1.0f - f.w);
    }
    ((float4*)g_cA)[ck * NC4 + c4] = A;
    ((float4*)g_cB)[ck * NC4 + c4] = Bv;
}

__global__ __launch_bounds__(256) void scan_combine_kernel() {
    const int c4 = blockIdx.x * 256 + threadIdx.x;   // 0..4095
    float4 h = make_float4(0.f, 0.f, 0.f, 0.f);
    #pragma unroll
    for (int c = 0; c < NCHUNK; c++) {
        ((float4*)g_cH)[c * NC4 + c4] = h;
        const float4 A = ((const float4*)g_cA)[c * NC4 + c4];
        const float4 Bv = ((const float4*)g_cB)[c * NC4 + c4];
        h.x = fmaf(A.x, h.x, Bv.x);
        h.y = fmaf(A.y, h.y, Bv.y);
        h.z = fmaf(A.z, h.z, Bv.z);
        h.w = fmaf(A.w, h.w, Bv.w);
    }
}

__global__ __launch_bounds__(256) void scan_final_kernel(float* __restrict__ out) {
    const int c4 = blockIdx.x * 256 + threadIdx.x;
    const int ck = blockIdx.y;
    const float4* F4 = (const float4*)g_F;
    const float4* Z4 = (const float4*)g_Z;
    const float4* O4 = (const float4*)g_O;
    float4* out4 = (float4*)out;
    size_t idx = (size_t)ck * CLEN * NC4 + c4;
    float4 h = ((const float4*)g_cH)[ck * NC4 + c4];
    #pragma unroll 4
    for (int s = 0; s < CLEN; s++, idx += NC4) {
        const float4 f = F4[idx];
        const float4 z = Z4[idx];
        const float4 o = O4[idx];
        h.x = fmaf(f.x, z.x - h.x, h.x);
        h.y = fmaf(f.y, z.y - h.y, h.y);
        h.z = fmaf(f.z, z.z - h.z, h.z);
        h.w = fmaf(f.w, z.w - h.w, h.w);
        out4[idx] = make_float4(o.x * h.x, o.y * h.y, o.z * h.z, o.w * h.w);
    }
    if (ck == NCHUNK - 1)
        out4[(size_t)MDIM * HDIM / 4 + c4] = h;   // C[-1]
}

// ---------------------------------------------------------------------------
extern "C" void kernel_launch(void* const* d_in, const int* in_sizes, int n_in,
                              void* d_out, int out_size) {
    const float* X    = (const float*)d_in[0];
    const float* W    = (const float*)d_in[1];
    const float* bias = (const float*)d_in[2];
    float* out = (float*)d_out;

    cudaFuncSetAttribute(gemm_hmma_kernel,
                         cudaFuncAttributeMaxDynamicSharedMemorySize, GEMM_SMEM);

    conv_kernel<true><<<(MDIM * KDIM / 4) / 256, 256>>>((const float4*)X);
    conv_kernel<false><<<(NDIM * KDIM / 4) / 256, 256>>>((const float4*)W);

    dim3 ggrid(NDIM / BN, MDIM / BM);   // (24, 128)
    gemm_hmma_kernel<<<ggrid, 256, GEMM_SMEM>>>(bias);

    dim3 sgrid(NC4 / 256, NCHUNK);      // (16, 16)
    scan_chunks_kernel<<<sgrid, 256>>>();
    scan_combine_kernel<<<NC4 / 256, 256>>>();
    scan_final_kernel<<<sgrid, 256>>>(out);
}